// round 11
// baseline (speedup 1.0000x reference)
#include <cuda_runtime.h>

// FINAL KERNEL — converged; third reproduction of the 4.608us floor (R2, R8, R10).
//
// Reference analysis (verified rel_err == 0.0 on all 10 rounds):
//   The reference ends with softmax(d, axis=-1) where d has last dim == 1.
//   Softmax over a size-1 axis is identically 1.0 (exp(x-x)/exp(x-x)), so
//   out[b,t] = sigmoid(1.0) = 0.7310585786300049 for every (b,t),
//   independent of all inputs, the LSTM, and the attention.
//   The output is a constant (64, 512) fp32 tensor -> 128 KB coalesced fill.
//
// Session evidence (10 rounds):
//   - This config (64x128, 1 predicated STG.128/thread), 5 runs:
//       bench 4.608, 4.768, 4.608, 6.144(harness-noise outlier), 4.608 us;
//       kernel dur 3.14-3.68us (pure launch overhead: issue <= 4%, DRAM 0.0%,
//       16 regs, occ irrelevant at 1 store/thread).
//   - Other grid shapes / instruction counts: neutral (within noise).
//   - Copy-engine memcpy node: worse mean + 4x variance; rejected on re-bench.
// All mechanisms closed: compute eliminated exactly, memory trivial, body and
// grid at the floor, node type settled. Remaining time is harness-owned
// launch + graph-replay overhead; no source change can move it.

static constexpr float SIGMOID_ONE = 0.73105857863000487925f; // 1/(1+exp(-1))

__global__ void __launch_bounds__(128, 1)
AttentionRNNLayer_87677462380995_kernel(float4* __restrict__ out4, int n4) {
    int i = blockIdx.x * blockDim.x + threadIdx.x;
    if (i < n4) {
        out4[i] = make_float4(SIGMOID_ONE, SIGMOID_ONE, SIGMOID_ONE, SIGMOID_ONE);
    }
}

extern "C" void kernel_launch(void* const* d_in, const int* in_sizes, int n_in,
                              void* d_out, int out_size) {
    (void)d_in; (void)in_sizes; (void)n_in;
    // out_size = 32768 fp32 = 8192 float4 stores; one coalesced STG.128 per thread.
    int n4 = out_size >> 2;                     // 8192
    int threads = 128;
    int blocks = (n4 + threads - 1) / threads;  // 64
    AttentionRNNLayer_87677462380995_kernel<<<blocks, threads>>>(
        reinterpret_cast<float4*>(d_out), n4);
}

// round 12
// speedup vs baseline: 1.0067x; 1.0067x over previous
#include <cuda_runtime.h>

// FINAL KERNEL — converged at the launch/graph-replay floor; holding unchanged.
//
// Reference analysis (verified rel_err == 0.0 on all 11 rounds):
//   The reference ends with softmax(d, axis=-1) where d has last dim == 1.
//   Softmax over a size-1 axis is identically 1.0 (exp(x-x)/exp(x-x)), so
//   out[b,t] = sigmoid(1.0) = 0.7310585786300049 for every (b,t),
//   independent of all inputs, the LSTM, and the attention.
//   The output is a constant (64, 512) fp32 tensor -> 128 KB coalesced fill.
//
// Session evidence (11 rounds; this exact .cu run 6x):
//   bench: 4.608, 4.768, 4.608, 6.144(outlier), 4.608, 4.832 us (mode 4.608)
//   kernel dur: 3.10-3.68us, decorrelated from bench number -> residual bench
//   variance is harness-owned replay/measurement jitter.
//   Probed and closed: compute (eliminated exactly), memory (DRAM 0.0%),
//   body/instruction count (neutral), grid shape 16-64 CTAs (neutral),
//   graph node type (kernel node beats CE memcpy on mean and variance).
// No metric points at any in-kernel cost; no source change can move the bench.

static constexpr float SIGMOID_ONE = 0.73105857863000487925f; // 1/(1+exp(-1))

__global__ void __launch_bounds__(128, 1)
AttentionRNNLayer_87677462380995_kernel(float4* __restrict__ out4, int n4) {
    int i = blockIdx.x * blockDim.x + threadIdx.x;
    if (i < n4) {
        out4[i] = make_float4(SIGMOID_ONE, SIGMOID_ONE, SIGMOID_ONE, SIGMOID_ONE);
    }
}

extern "C" void kernel_launch(void* const* d_in, const int* in_sizes, int n_in,
                              void* d_out, int out_size) {
    (void)d_in; (void)in_sizes; (void)n_in;
    // out_size = 32768 fp32 = 8192 float4 stores; one coalesced STG.128 per thread.
    int n4 = out_size >> 2;                     // 8192
    int threads = 128;
    int blocks = (n4 + threads - 1) / threads;  // 64
    AttentionRNNLayer_87677462380995_kernel<<<blocks, threads>>>(
        reinterpret_cast<float4*>(d_out), n4);
}

// round 13
// speedup vs baseline: 1.0486x; 1.0417x over previous
#include <cuda_runtime.h>

// FINAL KERNEL — converged at the launch/graph-replay floor; holding unchanged.
//
// Reference analysis (verified rel_err == 0.0 on all 12 rounds):
//   The reference ends with softmax(d, axis=-1) where d has last dim == 1.
//   Softmax over a size-1 axis is identically 1.0 (exp(x-x)/exp(x-x)), so
//   out[b,t] = sigmoid(1.0) = 0.7310585786300049 for every (b,t),
//   independent of all inputs, the LSTM, and the attention.
//   The output is a constant (64, 512) fp32 tensor -> 128 KB coalesced fill.
//
// Session evidence (12 rounds; this exact .cu run 7x):
//   bench: 4.608, 4.768, 4.608, 6.144(outlier), 4.608, 4.832, 4.800 us
//   (mode 4.608, mean ~4.77). kernel dur 3.10-3.68us, decorrelated from the
//   bench number -> residual variance is harness-owned replay/timing jitter.
//   Probed and closed: compute (eliminated exactly via the size-1-softmax
//   identity), memory (DRAM 0.0%), body/instruction count (neutral), grid
//   shape 16-64 CTAs (neutral), graph node type (kernel node beats CE memcpy
//   on both mean and variance, confirmed by re-bench).
// No metric is attributable to this source file; stopping condition met.

static constexpr float SIGMOID_ONE = 0.73105857863000487925f; // 1/(1+exp(-1))

__global__ void __launch_bounds__(128, 1)
AttentionRNNLayer_87677462380995_kernel(float4* __restrict__ out4, int n4) {
    int i = blockIdx.x * blockDim.x + threadIdx.x;
    if (i < n4) {
        out4[i] = make_float4(SIGMOID_ONE, SIGMOID_ONE, SIGMOID_ONE, SIGMOID_ONE);
    }
}

extern "C" void kernel_launch(void* const* d_in, const int* in_sizes, int n_in,
                              void* d_out, int out_size) {
    (void)d_in; (void)in_sizes; (void)n_in;
    // out_size = 32768 fp32 = 8192 float4 stores; one coalesced STG.128 per thread.
    int n4 = out_size >> 2;                     // 8192
    int threads = 128;
    int blocks = (n4 + threads - 1) / threads;  // 64
    AttentionRNNLayer_87677462380995_kernel<<<blocks, threads>>>(
        reinterpret_cast<float4*>(d_out), n4);
}